// round 2
// baseline (speedup 1.0000x reference)
#include <cuda_runtime.h>

// Problem constants (fixed by the dataset)
#define SB   1024      // species per batch row
#define N1   8192      // 1st-order reactions
#define N2   16384     // 2nd-order reactions
#define NSS  256       // surface / mantle species count
#define NT   256       // threads per CTA

__inline__ __device__ float warp_red(float v) {
    #pragma unroll
    for (int o = 16; o > 0; o >>= 1) v += __shfl_xor_sync(0xFFFFFFFFu, v, o);
    return v;
}

__global__ __launch_bounds__(NT) void three_phase_rhs(
    const float* __restrict__ t_in,      // [B]
    const float* __restrict__ y_in,      // [B,SB]
    const float* __restrict__ den_gas,   // [B]
    const float* __restrict__ a1,        // [N1]
    const float* __restrict__ g1,        // [N1]
    const float* __restrict__ a2,        // [N2]
    const float* __restrict__ g2,        // [N2]
    const int*   __restrict__ r1_1,      // [N1]
    const int*   __restrict__ p_1,       // [N1]
    const int*   __restrict__ r1_2,      // [N2]
    const int*   __restrict__ r2_2,      // [N2]
    const int*   __restrict__ p_2,       // [N2]
    const int*   __restrict__ inds_s,    // [NSS] contiguous
    const int*   __restrict__ inds_m,    // [NSS] contiguous
    float*       __restrict__ out)       // [B,SB]
{
    __shared__ float ysh[SB];
    __shared__ float dysh[SB];
    __shared__ float red[4][NT / 32];
    __shared__ float tot[4];

    const int b   = blockIdx.x;
    const int tid = threadIdx.x;

    const float* yrow = y_in + (size_t)b * SB;
    #pragma unroll
    for (int i = tid; i < SB; i += NT) { ysh[i] = yrow[i]; dysh[i] = 0.0f; }

    // per-batch scalars
    const float t     = t_in[b];
    const float T     = 10.0f + 5.0f / (1.0f + __expf(-t));
    const float nInvT = -1.0f / T;
    const float c2    = sqrtf(T * (1.0f / 300.0f)) * den_gas[b];
    const int   s0    = __ldg(&inds_s[0]);  // surface slots are s0..s0+NSS-1 (contiguous)

    __syncthreads();

    float gain = 0.0f, loss = 0.0f;

    // ---- 1st-order reactions (vectorized constant loads, 128b) ----
    for (int j4 = tid * 4; j4 < N1; j4 += NT * 4) {
        const float4 av = *(const float4*)(a1   + j4);
        const float4 gv = *(const float4*)(g1   + j4);
        const int4   rv = *(const int4*)  (r1_1 + j4);
        const int4   pv = *(const int4*)  (p_1  + j4);
        const float af[4] = {av.x, av.y, av.z, av.w};
        const float gf[4] = {gv.x, gv.y, gv.z, gv.w};
        const int   rf[4] = {rv.x, rv.y, rv.z, rv.w};
        const int   pf[4] = {pv.x, pv.y, pv.z, pv.w};
        #pragma unroll
        for (int k = 0; k < 4; k++) {
            const float term = af[k] * __expf(gf[k] * nInvT) * ysh[rf[k]];
            atomicAdd(&dysh[pf[k]],  term);
            atomicAdd(&dysh[rf[k]], -term);
            if ((unsigned)(pf[k] - s0) < NSS) gain += term;
            if ((unsigned)(rf[k] - s0) < NSS) loss += term;
        }
    }

    // ---- 2nd-order reactions ----
    for (int j4 = tid * 4; j4 < N2; j4 += NT * 4) {
        const float4 av = *(const float4*)(a2   + j4);
        const float4 gv = *(const float4*)(g2   + j4);
        const int4   r1v = *(const int4*) (r1_2 + j4);
        const int4   r2v = *(const int4*) (r2_2 + j4);
        const int4   pv  = *(const int4*) (p_2  + j4);
        const float af[4] = {av.x, av.y, av.z, av.w};
        const float gf[4] = {gv.x, gv.y, gv.z, gv.w};
        const int   rA[4] = {r1v.x, r1v.y, r1v.z, r1v.w};
        const int   rB[4] = {r2v.x, r2v.y, r2v.z, r2v.w};
        const int   pf[4] = {pv.x, pv.y, pv.z, pv.w};
        #pragma unroll
        for (int k = 0; k < 4; k++) {
            const float term = af[k] * __expf(gf[k] * nInvT) * c2 * ysh[rA[k]] * ysh[rB[k]];
            atomicAdd(&dysh[pf[k]],  term);
            atomicAdd(&dysh[rA[k]], -term);
            atomicAdd(&dysh[rB[k]], -term);
            if ((unsigned)(pf[k] - s0) < NSS) gain += term;
            if ((unsigned)(rA[k] - s0) < NSS) loss += term;
            if ((unsigned)(rB[k] - s0) < NSS) loss += term;
        }
    }

    // ---- block reductions: gain, loss, y_surf_tot, y_mant_tot ----
    const int si = __ldg(&inds_s[tid]);   // NT == NSS
    const int mi = __ldg(&inds_m[tid]);
    float ys = ysh[si];
    float ym = ysh[mi];

    const int lane = tid & 31, w = tid >> 5;
    gain = warp_red(gain);
    loss = warp_red(loss);
    ys   = warp_red(ys);
    ym   = warp_red(ym);
    if (lane == 0) { red[0][w] = gain; red[1][w] = loss; red[2][w] = ys; red[3][w] = ym; }
    __syncthreads();          // also orders all shared atomics before the epilogue
    if (tid < 4) {
        float s = 0.0f;
        #pragma unroll
        for (int i = 0; i < NT / 32; i++) s += red[tid][i];
        tot[tid] = s;
    }
    __syncthreads();

    const float k_s2m = tot[0] / (tot[2] + 1e-10f);   // gain / (y_surf_tot + eps)
    const float k_m2s = tot[1] / (tot[3] + 1e-10f);   // loss / (y_mant_tot + eps)

    // surface/mantle transfer: each thread owns one distinct (si, mi) pair
    const float s2m = k_s2m * ysh[si];
    const float m2s = k_m2s * ysh[mi];
    dysh[si] += m2s - s2m;
    dysh[mi] += s2m - m2s;
    __syncthreads();

    float* orow = out + (size_t)b * SB;
    #pragma unroll
    for (int i = tid; i < SB; i += NT) orow[i] = dysh[i];
}

extern "C" void kernel_launch(void* const* d_in, const int* in_sizes, int n_in,
                              void* d_out, int out_size) {
    const float* t_in    = (const float*)d_in[0];
    const float* y_in    = (const float*)d_in[1];
    const float* den_gas = (const float*)d_in[2];
    const float* a1      = (const float*)d_in[3];
    const float* g1      = (const float*)d_in[4];
    const float* a2      = (const float*)d_in[5];
    const float* g2      = (const float*)d_in[6];
    const int*   r1_1    = (const int*)d_in[7];
    const int*   p_1     = (const int*)d_in[8];
    const int*   r1_2    = (const int*)d_in[9];
    const int*   r2_2    = (const int*)d_in[10];
    const int*   p_2     = (const int*)d_in[11];
    const int*   inds_s  = (const int*)d_in[12];
    const int*   inds_m  = (const int*)d_in[13];
    float*       out     = (float*)d_out;

    const int B = in_sizes[0];
    three_phase_rhs<<<B, NT>>>(t_in, y_in, den_gas, a1, g1, a2, g2,
                               r1_1, p_1, r1_2, r2_2, p_2, inds_s, inds_m, out);
}

// round 3
// speedup vs baseline: 1.5447x; 1.5447x over previous
#include <cuda_runtime.h>

// ---- problem constants ----
#define SB      1024              // species per batch row
#define N1      8192
#define N2      16384
#define NTERMS  (N1 + N2)         // 24576
#define DUMMY   NTERMS            // dummy term index (reads zero)
#define NSS     256
#define NT      512               // threads in main kernel
#define ROWS    2                 // batch rows per CTA
#define LIST_CAP (NTERMS * 3)     // 73728 >= 65536 + 7*1024 padding

// ---- persistent scratch (constant across a launch; rebuilt every launch) ----
__device__ int g_counts[SB];
__device__ int g_cursor[SB];
__device__ int g_offs[SB + 1];
__device__ __align__(16) unsigned short g_list[LIST_CAP];

// smem: terms[2*(NTERMS+4)] | ysh0[SB] | ysh1[SB] | offs[SB+1]
#define TERMS_F   (2 * (NTERMS + 4))
#define SMEM_BYTES ((TERMS_F + 2 * SB) * 4 + (SB + 1) * 4)

// ---------- fast exp on the FMA pipe (valid for e in [-80, 0]) ----------
__device__ __forceinline__ float fexp(float e) {
    float t = e * 1.442695041f;                    // log2(e)
    float z = __fadd_rn(t, 12582912.0f);           // round-to-nearest magic (1.5*2^23)
    int   i = __float_as_int(z) - 0x4B400000;      // = round(t)
    float r = t - (z - 12582912.0f);               // r in [-0.5, 0.5]
    float p = 1.5403530e-4f;                       // 2^r Taylor, deg 6
    p = fmaf(p, r, 1.3333558e-3f);
    p = fmaf(p, r, 9.6181291e-3f);
    p = fmaf(p, r, 5.5504108e-2f);
    p = fmaf(p, r, 2.4022650e-1f);
    p = fmaf(p, r, 6.9314718e-1f);
    p = fmaf(p, r, 1.0f);
    return __int_as_float(__float_as_int(p) + (i << 23));
}

__inline__ __device__ float warp_red(float v) {
    #pragma unroll
    for (int o = 16; o > 0; o >>= 1) v += __shfl_xor_sync(0xFFFFFFFFu, v, o);
    return v;
}

// ---------- CSR build kernels (structure only depends on index inputs) ----------
__global__ void k_init() {
    int i = blockIdx.x * blockDim.x + threadIdx.x;
    if (i < SB) g_counts[i] = 0;
    if (i < LIST_CAP) g_list[i] = (unsigned short)DUMMY;
}

__global__ void k_count(const int* __restrict__ r11, const int* __restrict__ p1,
                        const int* __restrict__ r12, const int* __restrict__ r22,
                        const int* __restrict__ p2) {
    int i = blockIdx.x * blockDim.x + threadIdx.x;
    if (i >= NTERMS) return;
    if (i < N1) {
        atomicAdd(&g_counts[p1[i]], 1);
        atomicAdd(&g_counts[r11[i]], 1);
    } else {
        int j = i - N1;
        atomicAdd(&g_counts[p2[j]], 1);
        atomicAdd(&g_counts[r12[j]], 1);
        atomicAdd(&g_counts[r22[j]], 1);
    }
}

__global__ void k_scan() {     // 1 CTA, SB threads: exclusive scan of padded counts
    __shared__ int sh[SB];
    int t = threadIdx.x;
    int pc = (g_counts[t] + 7) & ~7;       // pad each list to multiple of 8 entries
    sh[t] = pc;
    __syncthreads();
    for (int o = 1; o < SB; o <<= 1) {
        int x = (t >= o) ? sh[t - o] : 0;
        __syncthreads();
        sh[t] += x;
        __syncthreads();
    }
    int excl = sh[t] - pc;
    g_offs[t] = excl;
    g_cursor[t] = excl;
    if (t == SB - 1) g_offs[SB] = sh[t];
}

__global__ void k_fill(const int* __restrict__ r11, const int* __restrict__ p1,
                       const int* __restrict__ r12, const int* __restrict__ r22,
                       const int* __restrict__ p2) {
    int i = blockIdx.x * blockDim.x + threadIdx.x;
    if (i >= NTERMS) return;
    if (i < N1) {
        unsigned short e = (unsigned short)i;
        g_list[atomicAdd(&g_cursor[p1[i]], 1)] = e;                     // gain
        g_list[atomicAdd(&g_cursor[r11[i]], 1)] = e | 0x8000u;          // loss
    } else {
        int j = i - N1;
        unsigned short e = (unsigned short)(N1 + j);
        g_list[atomicAdd(&g_cursor[p2[j]], 1)] = e;
        g_list[atomicAdd(&g_cursor[r12[j]], 1)] = e | 0x8000u;
        g_list[atomicAdd(&g_cursor[r22[j]], 1)] = e | 0x8000u;
    }
}

// ---------- main kernel: 2 batch rows per CTA, gather-only ----------
__global__ __launch_bounds__(NT, 1) void three_phase_rhs(
    const float* __restrict__ t_in, const float* __restrict__ y_in,
    const float* __restrict__ den_gas,
    const float* __restrict__ a1, const float* __restrict__ g1,
    const float* __restrict__ a2, const float* __restrict__ g2,
    const int* __restrict__ r11, const int* __restrict__ p1,
    const int* __restrict__ r12, const int* __restrict__ r22,
    const int* __restrict__ p2,
    const int* __restrict__ inds_s, const int* __restrict__ inds_m,
    float* __restrict__ out)
{
    extern __shared__ float smem[];
    float* terms = smem;                       // interleaved (row0,row1) per term
    float* ysh0  = terms + TERMS_F;
    float* ysh1  = ysh0 + SB;
    int*   offs  = (int*)(ysh1 + SB);
    __shared__ float red[8][NT / 32];
    __shared__ float tot[8];

    const int tid = threadIdx.x;
    const int b0 = blockIdx.x * ROWS, b1 = b0 + 1;

    const float* yr0 = y_in + (size_t)b0 * SB;
    const float* yr1 = y_in + (size_t)b1 * SB;
    #pragma unroll
    for (int i = tid; i < SB; i += NT) { ysh0[i] = yr0[i]; ysh1[i] = yr1[i]; }
    for (int i = tid; i <= SB; i += NT) offs[i] = g_offs[i];
    if (tid == 0) { terms[2 * DUMMY] = 0.0f; terms[2 * DUMMY + 1] = 0.0f; }

    const float T0 = 10.0f + 5.0f / (1.0f + fexp(-t_in[b0]));
    const float T1 = 10.0f + 5.0f / (1.0f + fexp(-t_in[b1]));
    const float nI0 = -1.0f / T0, nI1 = -1.0f / T1;
    const float c20 = sqrtf(T0 * (1.0f / 300.0f)) * den_gas[b0];
    const float c21 = sqrtf(T1 * (1.0f / 300.0f)) * den_gas[b1];
    const int s0 = __ldg(&inds_s[0]), m0 = __ldg(&inds_m[0]);   // contiguous ranges
    __syncthreads();

    // ---- phase 1: all reaction terms for both rows ----
    for (int j = tid; j < N1; j += NT) {
        float a = __ldg(a1 + j), g = __ldg(g1 + j);
        int   r = __ldg(r11 + j);
        float t0 = a * fexp(g * nI0) * ysh0[r];
        float t1 = a * fexp(g * nI1) * ysh1[r];
        *(float2*)&terms[2 * j] = make_float2(t0, t1);
    }
    for (int j = tid; j < N2; j += NT) {
        float a = __ldg(a2 + j), g = __ldg(g2 + j);
        int   rA = __ldg(r12 + j), rB = __ldg(r22 + j);
        float e0 = a * c20 * fexp(g * nI0);
        float e1 = a * c21 * fexp(g * nI1);
        float t0 = e0 * ysh0[rA] * ysh0[rB];
        float t1 = e1 * ysh1[rA] * ysh1[rB];
        *(float2*)&terms[2 * (N1 + j)] = make_float2(t0, t1);
    }
    __syncthreads();

    // ---- phase 2: gather per species (no atomics) ----
    float gain0 = 0, loss0 = 0, ysurf0 = 0, ymant0 = 0;
    float gain1 = 0, loss1 = 0, ysurf1 = 0, ymant1 = 0;
    float net[2][2];

    #pragma unroll
    for (int gsp = 0; gsp < 2; gsp++) {
        const int s = tid + gsp * NT;
        const int beg = offs[s], end = offs[s + 1];
        float p0 = 0, n0 = 0, p1v = 0, n1v = 0;
        for (int i = beg; i < end; i += 8) {
            uint4 q = *(const uint4*)(g_list + i);     // 8 packed entries
            unsigned w[4] = { q.x, q.y, q.z, q.w };
            #pragma unroll
            for (int u = 0; u < 4; u++) {
                unsigned e0 = w[u] & 0xFFFFu, e1 = w[u] >> 16;
                float2 tA = *(const float2*)&terms[(e0 & 0x7FFFu) * 2];
                float2 tB = *(const float2*)&terms[(e1 & 0x7FFFu) * 2];
                if (e0 & 0x8000u) { n0 += tA.x; n1v += tA.y; } else { p0 += tA.x; p1v += tA.y; }
                if (e1 & 0x8000u) { n0 += tB.x; n1v += tB.y; } else { p0 += tB.x; p1v += tB.y; }
            }
        }
        net[gsp][0] = p0 - n0;
        net[gsp][1] = p1v - n1v;
        unsigned ds = (unsigned)(s - s0), dm = (unsigned)(s - m0);
        if (ds < NSS) { gain0 += p0; loss0 += n0; gain1 += p1v; loss1 += n1v;
                        ysurf0 += ysh0[s]; ysurf1 += ysh1[s]; }
        if (dm < NSS) { ymant0 += ysh0[s]; ymant1 += ysh1[s]; }
    }

    // ---- block reductions (gain, loss, y_surf_tot, y_mant_tot) x 2 rows ----
    {
        float vals[8] = { gain0, loss0, ysurf0, ymant0, gain1, loss1, ysurf1, ymant1 };
        int lane = tid & 31, w = tid >> 5;
        #pragma unroll
        for (int v = 0; v < 8; v++) {
            float x = warp_red(vals[v]);
            if (lane == 0) red[v][w] = x;
        }
        __syncthreads();
        if (tid < 8) {
            float s = 0.0f;
            #pragma unroll
            for (int i = 0; i < NT / 32; i++) s += red[tid][i];
            tot[tid] = s;
        }
        __syncthreads();
    }
    const float ks2m0 = tot[0] / (tot[2] + 1e-10f);
    const float km2s0 = tot[1] / (tot[3] + 1e-10f);
    const float ks2m1 = tot[4] / (tot[6] + 1e-10f);
    const float km2s1 = tot[5] / (tot[7] + 1e-10f);

    float* o0 = out + (size_t)b0 * SB;
    float* o1 = out + (size_t)b1 * SB;
    #pragma unroll
    for (int gsp = 0; gsp < 2; gsp++) {
        const int s = tid + gsp * NT;
        float v0 = net[gsp][0], v1 = net[gsp][1];
        unsigned ds = (unsigned)(s - s0), dm = (unsigned)(s - m0);
        if (ds < NSS) {
            v0 += km2s0 * ysh0[m0 + ds] - ks2m0 * ysh0[s];
            v1 += km2s1 * ysh1[m0 + ds] - ks2m1 * ysh1[s];
        } else if (dm < NSS) {
            v0 += ks2m0 * ysh0[s0 + dm] - km2s0 * ysh0[s];
            v1 += ks2m1 * ysh1[s0 + dm] - km2s1 * ysh1[s];
        }
        o0[s] = v0;
        o1[s] = v1;
    }
}

extern "C" void kernel_launch(void* const* d_in, const int* in_sizes, int n_in,
                              void* d_out, int out_size) {
    const float* t_in    = (const float*)d_in[0];
    const float* y_in    = (const float*)d_in[1];
    const float* den_gas = (const float*)d_in[2];
    const float* a1      = (const float*)d_in[3];
    const float* g1      = (const float*)d_in[4];
    const float* a2      = (const float*)d_in[5];
    const float* g2      = (const float*)d_in[6];
    const int*   r11     = (const int*)d_in[7];
    const int*   p1      = (const int*)d_in[8];
    const int*   r12     = (const int*)d_in[9];
    const int*   r22     = (const int*)d_in[10];
    const int*   p2      = (const int*)d_in[11];
    const int*   inds_s  = (const int*)d_in[12];
    const int*   inds_m  = (const int*)d_in[13];
    float*       out     = (float*)d_out;

    const int B = in_sizes[0];

    cudaFuncSetAttribute(three_phase_rhs,
                         cudaFuncAttributeMaxDynamicSharedMemorySize, SMEM_BYTES);

    // rebuild CSR every launch (deterministic structure; order-only nondeterminism)
    k_init <<<(LIST_CAP + 255) / 256, 256>>>();
    k_count<<<(NTERMS + 255) / 256, 256>>>(r11, p1, r12, r22, p2);
    k_scan <<<1, SB>>>();
    k_fill <<<(NTERMS + 255) / 256, 256>>>(r11, p1, r12, r22, p2);

    three_phase_rhs<<<B / ROWS, NT, SMEM_BYTES>>>(
        t_in, y_in, den_gas, a1, g1, a2, g2,
        r11, p1, r12, r22, p2, inds_s, inds_m, out);
}

// round 4
// speedup vs baseline: 1.6851x; 1.0909x over previous
#include <cuda_runtime.h>

// ---- problem constants ----
#define SB      1024
#define N1      8192
#define N2      16384
#define NTERMS  (N1 + N2)          // 24576
#define CHUNK   12288              // terms per chunk (2 chunks)
#define NSS     256
#define NT      512
#define ROWS    4
#define NCTR    (2 * SB)           // (species, chunk) counters
#define NROLES  (2 * N1 + 3 * N2)  // 65536 scatter endpoints
#define LIST_CAP (NROLES + 7 * NCTR)   // 79872, each sublist padded to mult of 8

// ---- persistent scratch (rebuilt every launch; structure is input-constant) ----
__device__ int g_cnt[NCTR];
__device__ int g_cur[NCTR];
__device__ int g_off[NCTR + 1];
__device__ __align__(16) unsigned short g_list[LIST_CAP];

// smem: terms float4[CHUNK+1] | y float4[SB]
#define TERMS_BYTES ((CHUNK + 1) * 16)
#define SMEM_BYTES  (TERMS_BYTES + SB * 16)

// ---------- fast exp2-based expf on the FMA pipe (e in [-80, 0]) ----------
__device__ __forceinline__ float fexp(float e) {
    float t = e * 1.442695041f;
    float z = __fadd_rn(t, 12582912.0f);
    int   i = __float_as_int(z) - 0x4B400000;
    float r = t - (z - 12582912.0f);
    float p = 1.5403530e-4f;
    p = fmaf(p, r, 1.3333558e-3f);
    p = fmaf(p, r, 9.6181291e-3f);
    p = fmaf(p, r, 5.5504108e-2f);
    p = fmaf(p, r, 2.4022650e-1f);
    p = fmaf(p, r, 6.9314718e-1f);
    p = fmaf(p, r, 1.0f);
    return __int_as_float(__float_as_int(p) + (i << 23));
}

__inline__ __device__ float warp_red(float v) {
    #pragma unroll
    for (int o = 16; o > 0; o >>= 1) v += __shfl_xor_sync(0xFFFFFFFFu, v, o);
    return v;
}

// ---------- build kernels ----------
__global__ void k_zero() {
    int i = blockIdx.x * blockDim.x + threadIdx.x;
    if (i < NCTR) g_cnt[i] = 0;
}

__device__ __forceinline__ void decode_role(
    int id, const int* p1, const int* r11, const int* p2,
    const int* r12, const int* r22, int& term, int& s, bool& loss)
{
    if (id < N1)                { term = id;                   s = __ldg(p1  + id);            loss = false; }
    else if (id < 2 * N1)       { term = id - N1;              s = __ldg(r11 + id - N1);       loss = true;  }
    else if (id < 2 * N1 + N2)  { int j = id - 2 * N1;         term = N1 + j; s = __ldg(p2  + j);  loss = false; }
    else if (id < 2 * N1 + 2*N2){ int j = id - 2 * N1 - N2;    term = N1 + j; s = __ldg(r12 + j);  loss = true;  }
    else                        { int j = id - 2 * N1 - 2*N2;  term = N1 + j; s = __ldg(r22 + j);  loss = true;  }
}

__global__ void k_count(const int* __restrict__ p1, const int* __restrict__ r11,
                        const int* __restrict__ p2, const int* __restrict__ r12,
                        const int* __restrict__ r22) {
    int id = blockIdx.x * blockDim.x + threadIdx.x;
    if (id >= NROLES) return;
    int term, s; bool loss;
    decode_role(id, p1, r11, p2, r12, r22, term, s, loss);
    int c = (term >= CHUNK);
    atomicAdd(&g_cnt[2 * s + c], 1);
}

__global__ void k_scan() {   // 1 CTA, 1024 threads, 2048 counters
    __shared__ int pair[1024];
    int t = threadIdx.x;
    int c0 = (g_cnt[2 * t] + 7) & ~7;
    int c1 = (g_cnt[2 * t + 1] + 7) & ~7;
    pair[t] = c0 + c1;
    __syncthreads();
    for (int o = 1; o < 1024; o <<= 1) {
        int x = (t >= o) ? pair[t - o] : 0;
        __syncthreads();
        pair[t] += x;
        __syncthreads();
    }
    int excl = pair[t] - (c0 + c1);
    g_off[2 * t] = excl;       g_cur[2 * t] = excl;
    g_off[2 * t + 1] = excl + c0; g_cur[2 * t + 1] = excl + c0;
    if (t == 1023) g_off[NCTR] = pair[t];
}

__global__ void k_fill(const int* __restrict__ p1, const int* __restrict__ r11,
                       const int* __restrict__ p2, const int* __restrict__ r12,
                       const int* __restrict__ r22) {
    int id = blockIdx.x * blockDim.x + threadIdx.x;
    if (id >= NROLES) return;
    int term, s; bool loss;
    decode_role(id, p1, r11, p2, r12, r22, term, s, loss);
    int c = (term >= CHUNK);
    int pos = atomicAdd(&g_cur[2 * s + c], 1);
    g_list[pos] = (unsigned short)(term | (loss ? 0x8000 : 0));
}

__global__ void k_pad() {    // pad each sublist tail with chunk-local dummy
    int i = blockIdx.x * blockDim.x + threadIdx.x;
    if (i >= NCTR) return;
    int end = g_off[i + 1];
    unsigned short pv = (i & 1) ? (unsigned short)(2 * CHUNK) : (unsigned short)CHUNK;
    for (int p = g_cur[i]; p < end; p++) g_list[p] = pv;
}

// ---------- main kernel ----------
struct P2State {
    float net[2][4];   // per species-group, per row (signed net)
    float ng [2][4];   // loss-side sums (for surface gain/loss)
};

__device__ __forceinline__ void phase1(
    int base, float4* terms, const float4* y4,
    const float* a1, const float* g1, const float* a2, const float* g2,
    const int* r11, const int* r12, const int* r22,
    const float nI[4], const float c2[4], int tid)
{
    for (int jj = tid; jj < CHUNK; jj += NT) {
        int j = base + jj;
        float4 tv;
        if (j < N1) {
            float a = __ldg(a1 + j), g = __ldg(g1 + j);
            int   r = __ldg(r11 + j);
            float4 yv = y4[r];
            tv.x = a * fexp(g * nI[0]) * yv.x;
            tv.y = a * fexp(g * nI[1]) * yv.y;
            tv.z = a * fexp(g * nI[2]) * yv.z;
            tv.w = a * fexp(g * nI[3]) * yv.w;
        } else {
            int j2 = j - N1;
            float a = __ldg(a2 + j2), g = __ldg(g2 + j2);
            int  rA = __ldg(r12 + j2), rB = __ldg(r22 + j2);
            float4 ya = y4[rA], yb = y4[rB];
            tv.x = a * c2[0] * fexp(g * nI[0]) * ya.x * yb.x;
            tv.y = a * c2[1] * fexp(g * nI[1]) * ya.y * yb.y;
            tv.z = a * c2[2] * fexp(g * nI[2]) * ya.z * yb.z;
            tv.w = a * c2[3] * fexp(g * nI[3]) * ya.w * yb.w;
        }
        terms[jj] = tv;
    }
}

template <int CH>
__device__ __forceinline__ void phase2(
    P2State& st, const float4* terms,
    const int begv[2], const int endv[2], const bool isSurf[2])
{
    #pragma unroll
    for (int gsp = 0; gsp < 2; gsp++) {
        const int beg = begv[gsp], end = endv[gsp];
        const bool surf = isSurf[gsp];
        for (int i = beg; i < end; i += 8) {
            uint4 q = *(const uint4*)(g_list + i);
            unsigned w[4] = { q.x, q.y, q.z, q.w };
            #pragma unroll
            for (int u = 0; u < 4; u++) {
                #pragma unroll
                for (int h = 0; h < 2; h++) {
                    unsigned e = (h == 0) ? (w[u] & 0xFFFFu) : (w[u] >> 16);
                    int idx = (int)(e & 0x7FFFu) - CH * CHUNK;
                    float4 tv = terms[idx];
                    unsigned sx = (e & 0x8000u) << 16;   // sign into fp sign bit
                    st.net[gsp][0] += __int_as_float(__float_as_int(tv.x) ^ sx);
                    st.net[gsp][1] += __int_as_float(__float_as_int(tv.y) ^ sx);
                    st.net[gsp][2] += __int_as_float(__float_as_int(tv.z) ^ sx);
                    st.net[gsp][3] += __int_as_float(__float_as_int(tv.w) ^ sx);
                    if (surf && (e & 0x8000u)) {
                        st.ng[gsp][0] += tv.x;
                        st.ng[gsp][1] += tv.y;
                        st.ng[gsp][2] += tv.z;
                        st.ng[gsp][3] += tv.w;
                    }
                }
            }
        }
    }
}

__global__ __launch_bounds__(NT, 1) void three_phase_rhs(
    const float* __restrict__ t_in, const float* __restrict__ y_in,
    const float* __restrict__ den_gas,
    const float* __restrict__ a1, const float* __restrict__ g1,
    const float* __restrict__ a2, const float* __restrict__ g2,
    const int* __restrict__ r11, const int* __restrict__ r12,
    const int* __restrict__ r22,
    const int* __restrict__ inds_s, const int* __restrict__ inds_m,
    float* __restrict__ out)
{
    extern __shared__ float4 smem4[];
    float4* terms = smem4;                 // [CHUNK+1] (last = dummy, zero)
    float4* y4    = terms + (CHUNK + 1);   // [SB]
    __shared__ float red[16][NT / 32];
    __shared__ float tot[16];

    const int tid = threadIdx.x;
    const int b0 = blockIdx.x * ROWS;

    // load 4 y rows interleaved as float4
    {
        const float* yr0 = y_in + (size_t)b0 * SB;
        for (int i = tid; i < SB; i += NT) {
            y4[i] = make_float4(yr0[i], yr0[i + SB], yr0[i + 2 * SB], yr0[i + 3 * SB]);
        }
    }
    if (tid == 0) terms[CHUNK] = make_float4(0.f, 0.f, 0.f, 0.f);

    float nI[4], c2[4];
    #pragma unroll
    for (int r = 0; r < 4; r++) {
        float T = 10.0f + 5.0f / (1.0f + fexp(-__ldg(t_in + b0 + r)));
        nI[r] = -1.0f / T;
        c2[r] = sqrtf(T * (1.0f / 300.0f)) * __ldg(den_gas + b0 + r);
    }
    const int s0 = __ldg(&inds_s[0]), m0 = __ldg(&inds_m[0]);

    // per-thread species-group offsets (from L2)
    int begC0[2], endC0[2], endC1[2];
    bool isSurf[2], isMant[2];
    #pragma unroll
    for (int gsp = 0; gsp < 2; gsp++) {
        int s = tid + gsp * NT;
        begC0[gsp] = __ldg(&g_off[2 * s]);
        endC0[gsp] = __ldg(&g_off[2 * s + 1]);
        endC1[gsp] = __ldg(&g_off[2 * s + 2]);
        isSurf[gsp] = (unsigned)(s - s0) < NSS;
        isMant[gsp] = (unsigned)(s - m0) < NSS;
    }
    __syncthreads();

    P2State st;
    #pragma unroll
    for (int g = 0; g < 2; g++)
        #pragma unroll
        for (int r = 0; r < 4; r++) { st.net[g][r] = 0.f; st.ng[g][r] = 0.f; }

    // chunk 0
    phase1(0, terms, y4, a1, g1, a2, g2, r11, r12, r22, nI, c2, tid);
    __syncthreads();
    phase2<0>(st, terms, begC0, endC0, isSurf);
    __syncthreads();
    // chunk 1
    phase1(CHUNK, terms, y4, a1, g1, a2, g2, r11, r12, r22, nI, c2, tid);
    __syncthreads();
    phase2<1>(st, terms, endC0, endC1, isSurf);

    // ---- reductions: per row {gain, loss, ysurf, ymant} ----
    float vals[16];
    #pragma unroll
    for (int v = 0; v < 16; v++) vals[v] = 0.f;
    #pragma unroll
    for (int gsp = 0; gsp < 2; gsp++) {
        int s = tid + gsp * NT;
        if (isSurf[gsp]) {
            float4 yv = y4[s];
            float yr[4] = { yv.x, yv.y, yv.z, yv.w };
            #pragma unroll
            for (int r = 0; r < 4; r++) {
                vals[4 * r + 0] += st.net[gsp][r] + st.ng[gsp][r];  // gain
                vals[4 * r + 1] += st.ng[gsp][r];                   // loss
                vals[4 * r + 2] += yr[r];                           // y_surf_tot
            }
        } else if (isMant[gsp]) {
            float4 yv = y4[s];
            float yr[4] = { yv.x, yv.y, yv.z, yv.w };
            #pragma unroll
            for (int r = 0; r < 4; r++) vals[4 * r + 3] += yr[r];   // y_mant_tot
        }
    }
    {
        int lane = tid & 31, w = tid >> 5;
        #pragma unroll
        for (int v = 0; v < 16; v++) {
            float x = warp_red(vals[v]);
            if (lane == 0) red[v][w] = x;
        }
        __syncthreads();
        if (tid < 16) {
            float s = 0.f;
            #pragma unroll
            for (int i = 0; i < NT / 32; i++) s += red[tid][i];
            tot[tid] = s;
        }
        __syncthreads();
    }

    float ks2m[4], km2s[4];
    #pragma unroll
    for (int r = 0; r < 4; r++) {
        ks2m[r] = tot[4 * r + 0] / (tot[4 * r + 2] + 1e-10f);
        km2s[r] = tot[4 * r + 1] / (tot[4 * r + 3] + 1e-10f);
    }

    // ---- epilogue: transfer terms + write out ----
    #pragma unroll
    for (int gsp = 0; gsp < 2; gsp++) {
        int s = tid + gsp * NT;
        float dy[4];
        #pragma unroll
        for (int r = 0; r < 4; r++) dy[r] = st.net[gsp][r];
        unsigned ds = (unsigned)(s - s0), dm = (unsigned)(s - m0);
        if (ds < NSS) {
            float4 ym = y4[m0 + ds], ys = y4[s];
            float ymr[4] = { ym.x, ym.y, ym.z, ym.w };
            float ysr[4] = { ys.x, ys.y, ys.z, ys.w };
            #pragma unroll
            for (int r = 0; r < 4; r++) dy[r] += km2s[r] * ymr[r] - ks2m[r] * ysr[r];
        } else if (dm < NSS) {
            float4 ys = y4[s0 + dm], ym = y4[s];
            float ysr[4] = { ys.x, ys.y, ys.z, ys.w };
            float ymr[4] = { ym.x, ym.y, ym.z, ym.w };
            #pragma unroll
            for (int r = 0; r < 4; r++) dy[r] += ks2m[r] * ysr[r] - km2s[r] * ymr[r];
        }
        #pragma unroll
        for (int r = 0; r < 4; r++)
            out[(size_t)(b0 + r) * SB + s] = dy[r];
    }
}

extern "C" void kernel_launch(void* const* d_in, const int* in_sizes, int n_in,
                              void* d_out, int out_size) {
    const float* t_in    = (const float*)d_in[0];
    const float* y_in    = (const float*)d_in[1];
    const float* den_gas = (const float*)d_in[2];
    const float* a1      = (const float*)d_in[3];
    const float* g1      = (const float*)d_in[4];
    const float* a2      = (const float*)d_in[5];
    const float* g2      = (const float*)d_in[6];
    const int*   r11     = (const int*)d_in[7];
    const int*   p1      = (const int*)d_in[8];
    const int*   r12     = (const int*)d_in[9];
    const int*   r22     = (const int*)d_in[10];
    const int*   p2      = (const int*)d_in[11];
    const int*   inds_s  = (const int*)d_in[12];
    const int*   inds_m  = (const int*)d_in[13];
    float*       out     = (float*)d_out;

    const int B = in_sizes[0];

    cudaFuncSetAttribute(three_phase_rhs,
                         cudaFuncAttributeMaxDynamicSharedMemorySize, SMEM_BYTES);

    k_zero <<<(NCTR   + 255) / 256, 256>>>();
    k_count<<<(NROLES + 255) / 256, 256>>>(p1, r11, p2, r12, r22);
    k_scan <<<1, 1024>>>();
    k_fill <<<(NROLES + 255) / 256, 256>>>(p1, r11, p2, r12, r22);
    k_pad  <<<(NCTR   + 255) / 256, 256>>>();

    three_phase_rhs<<<B / ROWS, NT, SMEM_BYTES>>>(
        t_in, y_in, den_gas, a1, g1, a2, g2,
        r11, r12, r22, inds_s, inds_m, out);
}

// round 5
// speedup vs baseline: 1.6922x; 1.0042x over previous
#include <cuda_runtime.h>

// ---- problem constants ----
#define SB      1024
#define N1      8192
#define N2      16384
#define NTERMS  (N1 + N2)            // 24576
#define NC      5                    // chunks
#define CHUNK   5120                 // terms per chunk (last chunk = 4096)
#define NSS     256
#define NT      512
#define ROWS    8
#define NSUB    (2 * NC)             // sublists per species: (chunk, gain/loss)
#define NCTR    (SB * NSUB)          // 10240
#define NROLES  (2 * N1 + 3 * N2)    // 65536
#define LIST_CAP (NROLES + 7 * NCTR) // 137216

// ---- persistent scratch (rebuilt every launch; structure is input-constant) ----
__device__ int g_cnt[NCTR];
__device__ int g_cur[NCTR];
__device__ int g_off[NCTR + 1];
__device__ __align__(16) unsigned short g_list[LIST_CAP];

// dynamic smem: tlo float4[CHUNK+1] | thi float4[CHUNK+1] | ylo float4[SB] | yhi float4[SB]
#define SMEM_BYTES ((2 * (CHUNK + 1) + 2 * SB) * 16)

// ---------- fast exp (deg-5 2^r poly, FMA pipe; e in [-80, 0]) ----------
__device__ __forceinline__ float fexp(float e) {
    float t = e * 1.442695041f;
    float z = __fadd_rn(t, 12582912.0f);
    int   i = __float_as_int(z) - 0x4B400000;
    float r = t - (z - 12582912.0f);
    float p = 1.3333558e-3f;
    p = fmaf(p, r, 9.6181291e-3f);
    p = fmaf(p, r, 5.5504108e-2f);
    p = fmaf(p, r, 2.4022650e-1f);
    p = fmaf(p, r, 6.9314718e-1f);
    p = fmaf(p, r, 1.0f);
    return __int_as_float(__float_as_int(p) + (i << 23));
}

__inline__ __device__ float warp_red(float v) {
    #pragma unroll
    for (int o = 16; o > 0; o >>= 1) v += __shfl_xor_sync(0xFFFFFFFFu, v, o);
    return v;
}

// ---------- build kernels ----------
__global__ void k_zero() {
    int i = blockIdx.x * blockDim.x + threadIdx.x;
    if (i < NCTR) g_cnt[i] = 0;
}

__device__ __forceinline__ void decode_role(
    int id, const int* p1, const int* r11, const int* p2,
    const int* r12, const int* r22, int& term, int& s, int& loss)
{
    if (id < N1)                 { term = id;                  s = __ldg(p1  + id);          loss = 0; }
    else if (id < 2 * N1)        { term = id - N1;             s = __ldg(r11 + id - N1);     loss = 1; }
    else if (id < 2 * N1 + N2)   { int j = id - 2 * N1;        term = N1 + j; s = __ldg(p2  + j); loss = 0; }
    else if (id < 2 * N1 + 2*N2) { int j = id - 2 * N1 - N2;   term = N1 + j; s = __ldg(r12 + j); loss = 1; }
    else                         { int j = id - 2 * N1 - 2*N2; term = N1 + j; s = __ldg(r22 + j); loss = 1; }
}

__global__ void k_count(const int* __restrict__ p1, const int* __restrict__ r11,
                        const int* __restrict__ p2, const int* __restrict__ r12,
                        const int* __restrict__ r22) {
    int id = blockIdx.x * blockDim.x + threadIdx.x;
    if (id >= NROLES) return;
    int term, s, loss;
    decode_role(id, p1, r11, p2, r12, r22, term, s, loss);
    int c = term / CHUNK;
    atomicAdd(&g_cnt[s * NSUB + 2 * c + loss], 1);
}

__global__ void k_scan() {   // 1 CTA, 1024 threads, NSUB counters each
    __shared__ int sh[1024];
    int t = threadIdx.x;
    int pc[NSUB]; int tsum = 0;
    #pragma unroll
    for (int u = 0; u < NSUB; u++) {
        pc[u] = (g_cnt[t * NSUB + u] + 7) & ~7;
        tsum += pc[u];
    }
    sh[t] = tsum;
    __syncthreads();
    for (int o = 1; o < 1024; o <<= 1) {
        int x = (t >= o) ? sh[t - o] : 0;
        __syncthreads();
        sh[t] += x;
        __syncthreads();
    }
    int excl = sh[t] - tsum;
    #pragma unroll
    for (int u = 0; u < NSUB; u++) {
        g_off[t * NSUB + u] = excl;
        g_cur[t * NSUB + u] = excl;
        excl += pc[u];
    }
    if (t == 1023) g_off[NCTR] = sh[1023];
}

__global__ void k_fill(const int* __restrict__ p1, const int* __restrict__ r11,
                       const int* __restrict__ p2, const int* __restrict__ r12,
                       const int* __restrict__ r22) {
    int id = blockIdx.x * blockDim.x + threadIdx.x;
    if (id >= NROLES) return;
    int term, s, loss;
    decode_role(id, p1, r11, p2, r12, r22, term, s, loss);
    int c = term / CHUNK;
    int pos = atomicAdd(&g_cur[s * NSUB + 2 * c + loss], 1);
    g_list[pos] = (unsigned short)(term - c * CHUNK);   // chunk-local index
}

__global__ void k_pad() {    // pad sublist tails with dummy (terms[CHUNK] == 0)
    int i = blockIdx.x * blockDim.x + threadIdx.x;
    if (i >= NCTR) return;
    int end = g_off[i + 1];
    for (int p = g_cur[i]; p < end; p++) g_list[p] = (unsigned short)CHUNK;
}

// ---------- main kernel: 8 rows/CTA, 5 chunks, gather-only ----------
__global__ __launch_bounds__(NT, 1) void three_phase_rhs(
    const float* __restrict__ t_in, const float* __restrict__ y_in,
    const float* __restrict__ den_gas,
    const float* __restrict__ a1, const float* __restrict__ g1,
    const float* __restrict__ a2, const float* __restrict__ g2,
    const int* __restrict__ r11, const int* __restrict__ r12,
    const int* __restrict__ r22,
    const int* __restrict__ inds_s, const int* __restrict__ inds_m,
    float* __restrict__ out)
{
    extern __shared__ float4 smem4[];
    float4* tlo = smem4;                         // rows 0-3 per term
    float4* thi = tlo + (CHUNK + 1);             // rows 4-7 per term
    float4* ylo = thi + (CHUNK + 1);             // y rows 0-3
    float4* yhi = ylo + SB;                      // y rows 4-7
    __shared__ float red[32][NT / 32];
    __shared__ float tot[32];

    const int tid = threadIdx.x;
    const int b0 = blockIdx.x * ROWS;

    {
        const float* yr = y_in + (size_t)b0 * SB;
        for (int i = tid; i < SB; i += NT) {
            ylo[i] = make_float4(yr[i], yr[i + SB], yr[i + 2 * SB], yr[i + 3 * SB]);
            yhi[i] = make_float4(yr[i + 4 * SB], yr[i + 5 * SB], yr[i + 6 * SB], yr[i + 7 * SB]);
        }
    }
    if (tid == 0) {
        tlo[CHUNK] = make_float4(0.f, 0.f, 0.f, 0.f);
        thi[CHUNK] = make_float4(0.f, 0.f, 0.f, 0.f);
    }

    float nI[ROWS], c2[ROWS];
    #pragma unroll
    for (int r = 0; r < ROWS; r++) {
        float T = 10.0f + 5.0f / (1.0f + fexp(-__ldg(t_in + b0 + r)));
        nI[r] = -1.0f / T;
        c2[r] = sqrtf(T * (1.0f / 300.0f)) * __ldg(den_gas + b0 + r);
    }
    const int s0 = __ldg(&inds_s[0]), m0 = __ldg(&inds_m[0]);

    bool isSurf[2], isMant[2];
    #pragma unroll
    for (int gsp = 0; gsp < 2; gsp++) {
        int s = tid + gsp * NT;
        isSurf[gsp] = (unsigned)(s - s0) < NSS;
        isMant[gsp] = (unsigned)(s - m0) < NSS;
    }
    __syncthreads();

    float net[2][ROWS], ng[2][ROWS];
    #pragma unroll
    for (int g = 0; g < 2; g++)
        #pragma unroll
        for (int r = 0; r < ROWS; r++) { net[g][r] = 0.f; ng[g][r] = 0.f; }

    for (int c = 0; c < NC; c++) {
        const int base = c * CHUNK;
        const int clen = min(CHUNK, NTERMS - base);

        // ---- phase 1: terms for this chunk, all 8 rows ----
        for (int jj = tid; jj < clen; jj += NT) {
            int j = base + jj;
            float4 lo, hi;
            if (j < N1) {
                float a = __ldg(a1 + j), g = __ldg(g1 + j);
                int   rr = __ldg(r11 + j);
                float4 ya = ylo[rr], yb = yhi[rr];
                lo.x = a * fexp(g * nI[0]) * ya.x;
                lo.y = a * fexp(g * nI[1]) * ya.y;
                lo.z = a * fexp(g * nI[2]) * ya.z;
                lo.w = a * fexp(g * nI[3]) * ya.w;
                hi.x = a * fexp(g * nI[4]) * yb.x;
                hi.y = a * fexp(g * nI[5]) * yb.y;
                hi.z = a * fexp(g * nI[6]) * yb.z;
                hi.w = a * fexp(g * nI[7]) * yb.w;
            } else {
                int j2 = j - N1;
                float a = __ldg(a2 + j2), g = __ldg(g2 + j2);
                int  rA = __ldg(r12 + j2), rB = __ldg(r22 + j2);
                float4 yaA = ylo[rA], yaB = ylo[rB];
                float4 ybA = yhi[rA], ybB = yhi[rB];
                lo.x = a * c2[0] * fexp(g * nI[0]) * yaA.x * yaB.x;
                lo.y = a * c2[1] * fexp(g * nI[1]) * yaA.y * yaB.y;
                lo.z = a * c2[2] * fexp(g * nI[2]) * yaA.z * yaB.z;
                lo.w = a * c2[3] * fexp(g * nI[3]) * yaA.w * yaB.w;
                hi.x = a * c2[4] * fexp(g * nI[4]) * ybA.x * ybB.x;
                hi.y = a * c2[5] * fexp(g * nI[5]) * ybA.y * ybB.y;
                hi.z = a * c2[6] * fexp(g * nI[6]) * ybA.z * ybB.z;
                hi.w = a * c2[7] * fexp(g * nI[7]) * ybA.w * ybB.w;
            }
            tlo[jj] = lo;
            thi[jj] = hi;
        }
        __syncthreads();

        // ---- phase 2: gather this chunk's sublists (gain then loss, fused) ----
        #pragma unroll
        for (int gsp = 0; gsp < 2; gsp++) {
            const int s = tid + gsp * NT;
            const int ob = s * NSUB + 2 * c;
            const int beg     = __ldg(&g_off[ob]);
            const int lossBeg = __ldg(&g_off[ob + 1]);
            const int end     = __ldg(&g_off[ob + 2]);
            const bool surf = isSurf[gsp];
            for (int i = beg; i < end; i += 8) {
                const bool isLoss = (i >= lossBeg);        // uniform within group
                const float sgn = isLoss ? -1.0f : 1.0f;
                uint4 q = *(const uint4*)(g_list + i);
                unsigned w[4] = { q.x, q.y, q.z, q.w };
                #pragma unroll
                for (int u = 0; u < 4; u++) {
                    #pragma unroll
                    for (int h = 0; h < 2; h++) {
                        int e = (h == 0) ? (int)(w[u] & 0xFFFFu) : (int)(w[u] >> 16);
                        float4 lo = tlo[e], hi = thi[e];
                        net[gsp][0] = fmaf(sgn, lo.x, net[gsp][0]);
                        net[gsp][1] = fmaf(sgn, lo.y, net[gsp][1]);
                        net[gsp][2] = fmaf(sgn, lo.z, net[gsp][2]);
                        net[gsp][3] = fmaf(sgn, lo.w, net[gsp][3]);
                        net[gsp][4] = fmaf(sgn, hi.x, net[gsp][4]);
                        net[gsp][5] = fmaf(sgn, hi.y, net[gsp][5]);
                        net[gsp][6] = fmaf(sgn, hi.z, net[gsp][6]);
                        net[gsp][7] = fmaf(sgn, hi.w, net[gsp][7]);
                        if (surf && isLoss) {
                            ng[gsp][0] += lo.x; ng[gsp][1] += lo.y;
                            ng[gsp][2] += lo.z; ng[gsp][3] += lo.w;
                            ng[gsp][4] += hi.x; ng[gsp][5] += hi.y;
                            ng[gsp][6] += hi.z; ng[gsp][7] += hi.w;
                        }
                    }
                }
            }
        }
        __syncthreads();
    }

    // ---- reductions: per row {gain, loss, ysurf, ymant} ----
    float vals[32];
    #pragma unroll
    for (int v = 0; v < 32; v++) vals[v] = 0.f;
    #pragma unroll
    for (int gsp = 0; gsp < 2; gsp++) {
        int s = tid + gsp * NT;
        float4 ya = ylo[s], yb = yhi[s];
        float yr[ROWS] = { ya.x, ya.y, ya.z, ya.w, yb.x, yb.y, yb.z, yb.w };
        if (isSurf[gsp]) {
            #pragma unroll
            for (int r = 0; r < ROWS; r++) {
                vals[4 * r + 0] += net[gsp][r] + ng[gsp][r];  // gain
                vals[4 * r + 1] += ng[gsp][r];                // loss
                vals[4 * r + 2] += yr[r];                     // y_surf_tot
            }
        } else if (isMant[gsp]) {
            #pragma unroll
            for (int r = 0; r < ROWS; r++) vals[4 * r + 3] += yr[r];
        }
    }
    {
        int lane = tid & 31, w = tid >> 5;
        #pragma unroll
        for (int v = 0; v < 32; v++) {
            float x = warp_red(vals[v]);
            if (lane == 0) red[v][w] = x;
        }
        __syncthreads();
        if (tid < 32) {
            float s = 0.f;
            #pragma unroll
            for (int i = 0; i < NT / 32; i++) s += red[tid][i];
            tot[tid] = s;
        }
        __syncthreads();
    }

    float ks2m[ROWS], km2s[ROWS];
    #pragma unroll
    for (int r = 0; r < ROWS; r++) {
        ks2m[r] = tot[4 * r + 0] / (tot[4 * r + 2] + 1e-10f);
        km2s[r] = tot[4 * r + 1] / (tot[4 * r + 3] + 1e-10f);
    }

    // ---- epilogue: surface<->mantle transfer + write out ----
    #pragma unroll
    for (int gsp = 0; gsp < 2; gsp++) {
        int s = tid + gsp * NT;
        float dy[ROWS];
        #pragma unroll
        for (int r = 0; r < ROWS; r++) dy[r] = net[gsp][r];
        unsigned ds = (unsigned)(s - s0), dm = (unsigned)(s - m0);
        if (ds < NSS) {
            float4 ma = ylo[m0 + ds], mb = yhi[m0 + ds];
            float4 sa = ylo[s],       sb = yhi[s];
            float ymr[ROWS] = { ma.x, ma.y, ma.z, ma.w, mb.x, mb.y, mb.z, mb.w };
            float ysr[ROWS] = { sa.x, sa.y, sa.z, sa.w, sb.x, sb.y, sb.z, sb.w };
            #pragma unroll
            for (int r = 0; r < ROWS; r++) dy[r] += km2s[r] * ymr[r] - ks2m[r] * ysr[r];
        } else if (dm < NSS) {
            float4 sa = ylo[s0 + dm], sb = yhi[s0 + dm];
            float4 ma = ylo[s],       mb = yhi[s];
            float ysr[ROWS] = { sa.x, sa.y, sa.z, sa.w, sb.x, sb.y, sb.z, sb.w };
            float ymr[ROWS] = { ma.x, ma.y, ma.z, ma.w, mb.x, mb.y, mb.z, mb.w };
            #pragma unroll
            for (int r = 0; r < ROWS; r++) dy[r] += ks2m[r] * ysr[r] - km2s[r] * ymr[r];
        }
        #pragma unroll
        for (int r = 0; r < ROWS; r++)
            out[(size_t)(b0 + r) * SB + s] = dy[r];
    }
}

extern "C" void kernel_launch(void* const* d_in, const int* in_sizes, int n_in,
                              void* d_out, int out_size) {
    const float* t_in    = (const float*)d_in[0];
    const float* y_in    = (const float*)d_in[1];
    const float* den_gas = (const float*)d_in[2];
    const float* a1      = (const float*)d_in[3];
    const float* g1      = (const float*)d_in[4];
    const float* a2      = (const float*)d_in[5];
    const float* g2      = (const float*)d_in[6];
    const int*   r11     = (const int*)d_in[7];
    const int*   p1      = (const int*)d_in[8];
    const int*   r12     = (const int*)d_in[9];
    const int*   r22     = (const int*)d_in[10];
    const int*   p2      = (const int*)d_in[11];
    const int*   inds_s  = (const int*)d_in[12];
    const int*   inds_m  = (const int*)d_in[13];
    float*       out     = (float*)d_out;

    const int B = in_sizes[0];

    cudaFuncSetAttribute(three_phase_rhs,
                         cudaFuncAttributeMaxDynamicSharedMemorySize, SMEM_BYTES);

    k_zero <<<(NCTR   + 255) / 256, 256>>>();
    k_count<<<(NROLES + 255) / 256, 256>>>(p1, r11, p2, r12, r22);
    k_scan <<<1, 1024>>>();
    k_fill <<<(NROLES + 255) / 256, 256>>>(p1, r11, p2, r12, r22);
    k_pad  <<<(NCTR   + 255) / 256, 256>>>();

    three_phase_rhs<<<B / ROWS, NT, SMEM_BYTES>>>(
        t_in, y_in, den_gas, a1, g1, a2, g2,
        r11, r12, r22, inds_s, inds_m, out);
}